// round 2
// baseline (speedup 1.0000x reference)
#include <cuda_runtime.h>
#include <cstddef>

namespace {

constexpr int B = 2, N = 512, C = 64, H = 8;
constexpr int THREADS = 256;   // 8 warps; each warp owns 64 n-values of one (b,m) row

__global__ __launch_bounds__(THREADS, 2)
void mha_fused_kernel(const float* __restrict__ q,
                      const float* __restrict__ k,
                      const float* __restrict__ roi,
                      const float* __restrict__ W,
                      const float* __restrict__ bias,
                      float* __restrict__ out)
{
    __shared__ float wsum[8][H];

    const int tid  = threadIdx.x;
    const int bm   = blockIdx.x;            // b*N + m
    const int warp = tid >> 5;
    const int lane = tid & 31;
    const int hl   = lane & 15;             // lane within half-warp
    const int half = lane >> 4;             // 0 -> even n, 1 -> odd n
    const int c0   = hl * 4;                // this lane's channel slice

    // ---- W slice into registers: wq4[h] = W[h][c0..c0+3], wk4[h] = W[h][64+c0..] ----
    float4 wq4[H], wk4[H];
#pragma unroll
    for (int h = 0; h < H; ++h) {
        wq4[h] = *reinterpret_cast<const float4*>(W + h * 128 + c0);
        wk4[h] = *reinterpret_cast<const float4*>(W + h * 128 + 64 + c0);
    }
    float bs[H];
#pragma unroll
    for (int h = 0; h < H; ++h) bs[h] = bias[h];

    const float* qb = q   + (size_t)bm * N * C;
    const float* kb = k   + (size_t)bm * N * C;
    const float* rb = roi + (size_t)bm * N;

    const int nbase = warp * 64;

    float sA[H], sB[H];        // saved attn values, distributed: slot s holds iter s*16 + hl
    float sums[H];
#pragma unroll
    for (int h = 0; h < H; ++h) sums[h] = 0.f;

#pragma unroll 4
    for (int i = 0; i < 32; ++i) {
        const int n = nbase + 2 * i + half;   // half-warp 0 -> even, 1 -> odd

        // fully coalesced: 32 lanes x 16B contiguous per n-pair
        const float4 qv = *reinterpret_cast<const float4*>(qb + n * C + c0);
        const float4 kv = *reinterpret_cast<const float4*>(kb + n * C + c0);

        float p[H];
#pragma unroll
        for (int h = 0; h < H; ++h) {
            float t;
            t = qv.x * wq4[h].x;
            t = fmaf(qv.y, wq4[h].y, t);
            t = fmaf(qv.z, wq4[h].z, t);
            t = fmaf(qv.w, wq4[h].w, t);
            t = fmaf(kv.x, wk4[h].x, t);
            t = fmaf(kv.y, wk4[h].y, t);
            t = fmaf(kv.z, wk4[h].z, t);
            t = fmaf(kv.w, wk4[h].w, t);
            p[h] = t;
        }

        // reduce partial dots over the 16 lanes of each half-warp
#pragma unroll
        for (int off = 8; off >= 1; off >>= 1) {
#pragma unroll
            for (int h = 0; h < H; ++h)
                p[h] += __shfl_xor_sync(0xffffffffu, p[h], off);
        }

        const float r = rb[n];   // same address across a half-warp -> broadcast
#pragma unroll
        for (int h = 0; h < H; ++h) {
            const float e = __expf(p[h] + bs[h]) * r;
            sums[h] += e;                           // per-lane partial over its half's n's
            if ((i & 15) == hl) {                   // distribute storage across lanes
                if (i < 16) sA[h] = e; else sB[h] = e;
            }
        }
    }

    // ---- row-sum reduction ----
    // combine the two halves (each half saw a disjoint set of n)
#pragma unroll
    for (int h = 0; h < H; ++h)
        sums[h] += __shfl_xor_sync(0xffffffffu, sums[h], 16);
    if (lane == 0) {
#pragma unroll
        for (int h = 0; h < H; ++h) wsum[warp][h] = sums[h];
    }
    __syncthreads();

    float inv[H];
#pragma unroll
    for (int h = 0; h < H; ++h) {
        float t = 0.f;
#pragma unroll
        for (int w = 0; w < 8; ++w) t += wsum[w][h];
        inv[h] = 1.0f / t;
    }

    // ---- normalize + store (each lane stores its 2 saved n's: 2x STG.128 each) ----
    {
        const int n0 = nbase + 2 * (0 * 16 + hl) + half;
        float* op = out + ((size_t)bm * N + n0) * H;
        float4 a, b2;
        a.x  = sA[0] * inv[0];  a.y  = sA[1] * inv[1];
        a.z  = sA[2] * inv[2];  a.w  = sA[3] * inv[3];
        b2.x = sA[4] * inv[4];  b2.y = sA[5] * inv[5];
        b2.z = sA[6] * inv[6];  b2.w = sA[7] * inv[7];
        *reinterpret_cast<float4*>(op)     = a;
        *reinterpret_cast<float4*>(op + 4) = b2;
    }
    {
        const int n1 = nbase + 2 * (1 * 16 + hl) + half;
        float* op = out + ((size_t)bm * N + n1) * H;
        float4 a, b2;
        a.x  = sB[0] * inv[0];  a.y  = sB[1] * inv[1];
        a.z  = sB[2] * inv[2];  a.w  = sB[3] * inv[3];
        b2.x = sB[4] * inv[4];  b2.y = sB[5] * inv[5];
        b2.z = sB[6] * inv[6];  b2.w = sB[7] * inv[7];
        *reinterpret_cast<float4*>(op)     = a;
        *reinterpret_cast<float4*>(op + 4) = b2;
    }
}

} // namespace

extern "C" void kernel_launch(void* const* d_in, const int* in_sizes, int n_in,
                              void* d_out, int out_size)
{
    const float* q    = (const float*)d_in[0];
    const float* k    = (const float*)d_in[1];
    const float* roi  = (const float*)d_in[2];
    const float* W    = (const float*)d_in[3];
    const float* bias = (const float*)d_in[4];
    float* out        = (float*)d_out;

    (void)in_sizes; (void)n_in; (void)out_size;

    dim3 grid(B * N);     // one block per (b, m) row
    dim3 block(THREADS);
    mha_fused_kernel<<<grid, block>>>(q, k, roi, W, bias, out);
}

// round 3
// speedup vs baseline: 2.0507x; 2.0507x over previous
#include <cuda_runtime.h>
#include <cstddef>

namespace {

constexpr int B = 2, N = 512, C = 64, H = 8;
constexpr int THREADS = 256;
constexpr int RS = 36;              // buf row stride in floats (pad: 32 -> 36)

#define FMA2(acc, a, b) \
    asm("fma.rn.f32x2 %0, %1, %2, %0;" : "+l"(acc) : "l"(a), "l"(b))

__device__ __forceinline__ unsigned long long pack2(float lo, float hi) {
    unsigned long long d;
    unsigned int l = __float_as_uint(lo), h = __float_as_uint(hi);
    asm("mov.b64 %0, {%1, %2};" : "=l"(d) : "r"(l), "r"(h));
    return d;
}
__device__ __forceinline__ void unpack2(unsigned long long v, float& lo, float& hi) {
    unsigned int l, h;
    asm("mov.b64 {%0, %1}, %2;" : "=r"(l), "=r"(h) : "l"(v));
    lo = __uint_as_float(l);
    hi = __uint_as_float(h);
}

__global__ __launch_bounds__(THREADS)
void mha_fused_kernel(const float* __restrict__ q,
                      const float* __restrict__ k,
                      const float* __restrict__ roi,
                      const float* __restrict__ W,
                      const float* __restrict__ bias,
                      float* __restrict__ out)
{
    __shared__ float Ws[128 * H];           // [c][h], 4 KB
    __shared__ float buf[256 * RS];         // 36 KB stage buffer (256 rows x 32 ch, padded)
    __shared__ float wsum[8][H];

    const int tid  = threadIdx.x;
    const int bm   = blockIdx.x;            // b*N + m
    const int warp = tid >> 5;
    const int lane = tid & 31;

    // W[h][128] -> Ws[c][h]
    for (int i = tid; i < 128 * H; i += THREADS) {
        const int h = i >> 7, c = i & 127;
        Ws[c * H + h] = W[i];
    }

    unsigned long long bias2[4];
    {
        float bv[H];
#pragma unroll
        for (int h = 0; h < H; ++h) bv[h] = bias[h];
#pragma unroll
        for (int j = 0; j < 4; ++j) bias2[j] = pack2(bv[2 * j], bv[2 * j + 1]);
    }

    const float* qb = q   + (size_t)bm * N * C;
    const float* kb = k   + (size_t)bm * N * C;
    const float* rb = roi + (size_t)bm * N;

    float esv[2][H];
    float sums[H];
#pragma unroll
    for (int h = 0; h < H; ++h) sums[h] = 0.f;

#pragma unroll
    for (int half = 0; half < 2; ++half) {
        const int n = half * 256 + tid;

        unsigned long long acc[4];
#pragma unroll
        for (int j = 0; j < 4; ++j) acc[j] = bias2[j];

        // 4 stages: q cols 0-31, q cols 32-63, k cols 0-31, k cols 32-63
#pragma unroll
        for (int s = 0; s < 4; ++s) {
            const float* src = (s < 2 ? qb : kb) + (size_t)half * 256 * C + (s & 1) * 32;

            __syncthreads();   // previous stage's readers done
            // ---- stage 256 rows x 32 ch, fully line-aligned LDG.128 ----
#pragma unroll
            for (int i = 0; i < 8; ++i) {
                const int idx = i * THREADS + tid;      // 0..2047 float4
                const int row = idx >> 3, c4 = idx & 7;
                const float4 v = *reinterpret_cast<const float4*>(src + row * C + c4 * 4);
                *reinterpret_cast<float4*>(&buf[row * RS + c4 * 4]) = v;
            }
            __syncthreads();

            // ---- compute: thread t owns row t (conflict-free padded LDS) ----
            const float* brow = &buf[tid * RS];
            const int cbase = (s < 2 ? 0 : 64) + (s & 1) * 32;
            const ulonglong2* wp = reinterpret_cast<const ulonglong2*>(&Ws[cbase * H]);
#pragma unroll
            for (int c4i = 0; c4i < 8; ++c4i) {
                const float4 v = *reinterpret_cast<const float4*>(brow + c4i * 4);
                const float vv[4] = {v.x, v.y, v.z, v.w};
#pragma unroll
                for (int cc = 0; cc < 4; ++cc) {
                    const unsigned long long a2 = pack2(vv[cc], vv[cc]);
                    const int c = c4i * 4 + cc;
                    const ulonglong2 w01 = wp[c * 2];       // heads 0-3 (two pairs)
                    const ulonglong2 w45 = wp[c * 2 + 1];   // heads 4-7
                    FMA2(acc[0], a2, w01.x);
                    FMA2(acc[1], a2, w01.y);
                    FMA2(acc[2], a2, w45.x);
                    FMA2(acc[3], a2, w45.y);
                }
            }
        }

        // ---- epilogue for this half's row: exp * roi ----
        float av[H];
#pragma unroll
        for (int j = 0; j < 4; ++j) unpack2(acc[j], av[2 * j], av[2 * j + 1]);
        const float r = rb[n];
#pragma unroll
        for (int h = 0; h < H; ++h) {
            const float e = __expf(av[h]) * r;
            esv[half][h] = e;
            sums[h] += e;
        }
    }

    // ---- block-wide row-sum over all 512 n ----
#pragma unroll
    for (int h = 0; h < H; ++h) {
        float s = sums[h];
#pragma unroll
        for (int off = 16; off > 0; off >>= 1)
            s += __shfl_xor_sync(0xffffffffu, s, off);
        sums[h] = s;
    }
    if (lane == 0) {
#pragma unroll
        for (int h = 0; h < H; ++h) wsum[warp][h] = sums[h];
    }
    __syncthreads();

    float inv[H];
#pragma unroll
    for (int h = 0; h < H; ++h) {
        float t = 0.f;
#pragma unroll
        for (int w = 0; w < 8; ++w) t += wsum[w][h];
        inv[h] = 1.0f / t;
    }

    // ---- normalize + store: thread t stores rows n=t and n=t+256 ----
#pragma unroll
    for (int half = 0; half < 2; ++half) {
        const int n = half * 256 + tid;
        float* op = out + ((size_t)bm * N + n) * H;
        float4 a, b2;
        a.x  = esv[half][0] * inv[0];  a.y  = esv[half][1] * inv[1];
        a.z  = esv[half][2] * inv[2];  a.w  = esv[half][3] * inv[3];
        b2.x = esv[half][4] * inv[4];  b2.y = esv[half][5] * inv[5];
        b2.z = esv[half][6] * inv[6];  b2.w = esv[half][7] * inv[7];
        *reinterpret_cast<float4*>(op)     = a;
        *reinterpret_cast<float4*>(op + 4) = b2;
    }
}

} // namespace

extern "C" void kernel_launch(void* const* d_in, const int* in_sizes, int n_in,
                              void* d_out, int out_size)
{
    const float* q    = (const float*)d_in[0];
    const float* k    = (const float*)d_in[1];
    const float* roi  = (const float*)d_in[2];
    const float* W    = (const float*)d_in[3];
    const float* bias = (const float*)d_in[4];
    float* out        = (float*)d_out;

    (void)in_sizes; (void)n_in; (void)out_size;

    dim3 grid(B * N);     // one block per (b, m) row
    dim3 block(THREADS);
    mha_fused_kernel<<<grid, block>>>(q, k, roi, W, bias, out);
}

// round 4
// speedup vs baseline: 2.7250x; 1.3288x over previous
#include <cuda_runtime.h>
#include <cstddef>
#include <cstdint>

namespace {

constexpr int B = 2, N = 512, C = 64, H = 8;
constexpr int THREADS = 256;
constexpr int SCH    = 16;             // channels per stage
constexpr int STAGES = 8;              // 4 q-stages + 4 k-stages
constexpr int RSTR   = 20;             // buf row stride in floats (16 + 4 pad)
constexpr int BUF_FLOATS = 512 * RSTR; // one buffer
// dynamic smem layout: Ws[1024] | buf0 | buf1 | wsum[64]
constexpr size_t SMEM_BYTES = (1024 + 2 * BUF_FLOATS + 64) * sizeof(float);

#define FMA2(acc, a, b) \
    asm("fma.rn.f32x2 %0, %1, %2, %0;" : "+l"(acc) : "l"(a), "l"(b))

__device__ __forceinline__ unsigned long long pack2(float lo, float hi) {
    unsigned long long d;
    asm("mov.b64 %0, {%1, %2};" : "=l"(d) : "r"(__float_as_uint(lo)), "r"(__float_as_uint(hi)));
    return d;
}
__device__ __forceinline__ void unpack2(unsigned long long v, float& lo, float& hi) {
    unsigned int l, h;
    asm("mov.b64 {%0, %1}, %2;" : "=r"(l), "=r"(h) : "l"(v));
    lo = __uint_as_float(l);
    hi = __uint_as_float(h);
}
__device__ __forceinline__ uint32_t smem_u32(const void* p) {
    return (uint32_t)__cvta_generic_to_shared(p);
}
__device__ __forceinline__ void cp_async16(uint32_t dst, const void* src) {
    asm volatile("cp.async.cg.shared.global [%0], [%1], 16;" :: "r"(dst), "l"(src));
}

__global__ __launch_bounds__(THREADS, 2)
void mha_fused_kernel(const float* __restrict__ q,
                      const float* __restrict__ k,
                      const float* __restrict__ roi,
                      const float* __restrict__ W,
                      const float* __restrict__ bias,
                      float* __restrict__ out)
{
    extern __shared__ float smem[];
    float* Ws   = smem;                         // [c][h], 4 KB
    float* bufs = smem + 1024;                  // 2 x BUF_FLOATS
    float* wsum = smem + 1024 + 2 * BUF_FLOATS; // [8][H]

    const int tid  = threadIdx.x;
    const int bm   = blockIdx.x;                // b*N + m
    const int warp = tid >> 5;
    const int lane = tid & 31;

    const float* qb = q   + (size_t)bm * N * C;
    const float* kb = k   + (size_t)bm * N * C;
    const float* rb = roi + (size_t)bm * N;

    // W[h][128] -> Ws[c][h]
    for (int i = tid; i < 128 * H; i += THREADS) {
        const int h = i >> 7, c = i & 127;
        Ws[c * H + h] = W[i];
    }

    unsigned long long bias2[4];
    {
        float bv[H];
#pragma unroll
        for (int h = 0; h < H; ++h) bv[h] = bias[h];
#pragma unroll
        for (int j = 0; j < 4; ++j) bias2[j] = pack2(bv[2 * j], bv[2 * j + 1]);
    }

    // ---- stage issue helper: stage s = 16 channels for all 512 rows ----
    // src row base: q stages 0..3 at channel s*16, k stages 4..7 at channel (s-4)*16
    auto issue_stage = [&](int s) {
        const float* src = (s < 4 ? qb + s * SCH : kb + (s - 4) * SCH);
        float* dst = bufs + (s & 1) * BUF_FLOATS;
#pragma unroll
        for (int i = 0; i < 8; ++i) {
            const int idx = i * THREADS + tid;   // 0..2047 float4 slots
            const int row = idx >> 2, c4 = idx & 3;
            cp_async16(smem_u32(&dst[row * RSTR + c4 * 4]), src + (size_t)row * C + c4 * 4);
        }
        asm volatile("cp.async.commit_group;" ::: "memory");
    };

    issue_stage(0);

    unsigned long long acc0[4], acc1[4];
#pragma unroll
    for (int j = 0; j < 4; ++j) { acc0[j] = bias2[j]; acc1[j] = bias2[j]; }

#pragma unroll
    for (int s = 0; s < STAGES; ++s) {
        asm volatile("cp.async.wait_group 0;" ::: "memory");
        __syncthreads();                          // stage s data visible, stage s-1 readers done
        if (s + 1 < STAGES) issue_stage(s + 1);   // overlaps with compute below

        const float* base = bufs + (s & 1) * BUF_FLOATS;
        const float* r0 = base + tid * RSTR;
        const float* r1 = base + (tid + 256) * RSTR;

        float4 d0[4], d1[4];
#pragma unroll
        for (int j = 0; j < 4; ++j) {
            d0[j] = reinterpret_cast<const float4*>(r0)[j];
            d1[j] = reinterpret_cast<const float4*>(r1)[j];
        }

        const ulonglong2* wp = reinterpret_cast<const ulonglong2*>(&Ws[(s * SCH) * H]);
#pragma unroll
        for (int j = 0; j < 4; ++j) {
            const float v0[4] = {d0[j].x, d0[j].y, d0[j].z, d0[j].w};
            const float v1[4] = {d1[j].x, d1[j].y, d1[j].z, d1[j].w};
#pragma unroll
            for (int cc = 0; cc < 4; ++cc) {
                const int c = j * 4 + cc;
                const ulonglong2 w01 = wp[c * 2];       // heads 0-3
                const ulonglong2 w45 = wp[c * 2 + 1];   // heads 4-7
                const unsigned long long a0 = pack2(v0[cc], v0[cc]);
                const unsigned long long a1 = pack2(v1[cc], v1[cc]);
                FMA2(acc0[0], a0, w01.x);
                FMA2(acc0[1], a0, w01.y);
                FMA2(acc0[2], a0, w45.x);
                FMA2(acc0[3], a0, w45.y);
                FMA2(acc1[0], a1, w01.x);
                FMA2(acc1[1], a1, w01.y);
                FMA2(acc1[2], a1, w45.x);
                FMA2(acc1[3], a1, w45.y);
            }
        }
    }

    // ---- epilogue: exp * roi for both rows ----
    float e0[H], e1[H], sums[H];
    {
        float a0[H], a1[H];
#pragma unroll
        for (int j = 0; j < 4; ++j) {
            unpack2(acc0[j], a0[2 * j], a0[2 * j + 1]);
            unpack2(acc1[j], a1[2 * j], a1[2 * j + 1]);
        }
        const float r0v = rb[tid];
        const float r1v = rb[tid + 256];
#pragma unroll
        for (int h = 0; h < H; ++h) {
            e0[h] = __expf(a0[h]) * r0v;
            e1[h] = __expf(a1[h]) * r1v;
            sums[h] = e0[h] + e1[h];
        }
    }

    // ---- block-wide row-sum over all 512 n ----
#pragma unroll
    for (int h = 0; h < H; ++h) {
        float s = sums[h];
#pragma unroll
        for (int off = 16; off > 0; off >>= 1)
            s += __shfl_xor_sync(0xffffffffu, s, off);
        sums[h] = s;
    }
    if (lane == 0) {
#pragma unroll
        for (int h = 0; h < H; ++h) wsum[warp * H + h] = sums[h];
    }
    __syncthreads();

    float inv[H];
#pragma unroll
    for (int h = 0; h < H; ++h) {
        float t = 0.f;
#pragma unroll
        for (int w = 0; w < 8; ++w) t += wsum[w * H + h];
        inv[h] = 1.0f / t;
    }

    // ---- normalize + store ----
    {
        float* op = out + ((size_t)bm * N + tid) * H;
        float4 a, b2;
        a.x  = e0[0] * inv[0];  a.y  = e0[1] * inv[1];
        a.z  = e0[2] * inv[2];  a.w  = e0[3] * inv[3];
        b2.x = e0[4] * inv[4];  b2.y = e0[5] * inv[5];
        b2.z = e0[6] * inv[6];  b2.w = e0[7] * inv[7];
        *reinterpret_cast<float4*>(op)     = a;
        *reinterpret_cast<float4*>(op + 4) = b2;
    }
    {
        float* op = out + ((size_t)bm * N + tid + 256) * H;
        float4 a, b2;
        a.x  = e1[0] * inv[0];  a.y  = e1[1] * inv[1];
        a.z  = e1[2] * inv[2];  a.w  = e1[3] * inv[3];
        b2.x = e1[4] * inv[4];  b2.y = e1[5] * inv[5];
        b2.z = e1[6] * inv[6];  b2.w = e1[7] * inv[7];
        *reinterpret_cast<float4*>(op)     = a;
        *reinterpret_cast<float4*>(op + 4) = b2;
    }
}

} // namespace

extern "C" void kernel_launch(void* const* d_in, const int* in_sizes, int n_in,
                              void* d_out, int out_size)
{
    const float* q    = (const float*)d_in[0];
    const float* k    = (const float*)d_in[1];
    const float* roi  = (const float*)d_in[2];
    const float* W    = (const float*)d_in[3];
    const float* bias = (const float*)d_in[4];
    float* out        = (float*)d_out;

    (void)in_sizes; (void)n_in; (void)out_size;

    cudaFuncSetAttribute(mha_fused_kernel,
                         cudaFuncAttributeMaxDynamicSharedMemorySize,
                         (int)SMEM_BYTES);

    dim3 grid(B * N);     // one block per (b, m) row
    dim3 block(THREADS);
    mha_fused_kernel<<<grid, block, SMEM_BYTES>>>(q, k, roi, W, bias, out);
}